// round 12
// baseline (speedup 1.0000x reference)
#include <cuda_runtime.h>

#define B_  16
#define C_  8
#define H_  512
#define W_  512
#define TW  32           // tile width
#define TH  16           // tile height
#define HW_ 34           // TW + 2
#define HH_ 18           // TH + 2
#define SROW 35          // smem row stride (floats)
#define PLANE (C_ * HH_ * SROW)
#define NTHREADS 256
#define NBLOCKS ((W_/TW)*(H_/TH)*B_)     /* 8192 */
#define CHS ((size_t)H_ * W_)            /* channel stride */

__device__ double   g_acc;    // zero-initialized at module load
__device__ unsigned g_tick;   // zero-initialized at module load

__device__ __forceinline__ void sigmoid_pair(float x, float& p, float& lp) {
    float e  = __expf(-fabsf(x));            // EX2
    float op = 1.0f + e;
    float l  = __logf(op);                   // LG2 (= log1p(e), e<=1)
    float r  = __fdividef(1.0f, op);         // RCP
    p  = (x >= 0.0f) ? r : e * r;            // sigmoid(x)
    lp = fminf(x, 0.0f) - l;                 // log sigmoid(x)
}

__global__ __launch_bounds__(NTHREADS)
void k_main(const float* __restrict__ cmap,
            const float* __restrict__ target,
            const float* __restrict__ con,
            float* __restrict__ out) {
    __shared__ float s_p[PLANE];
    __shared__ float s_lp[PLANE];
    __shared__ unsigned char s_mask[TH * TW];   // packed con bits per pixel

    const int w0  = blockIdx.x * TW;
    const int h0  = blockIdx.y * TH;
    const int b   = blockIdx.z;
    const int tid = threadIdx.x;
    const int lane = tid & 31;
    const int wrp  = tid >> 5;     // 0..7

    float acc08 = 0.0f;   // conmap BCE terms (weight 0.8 applied at end)
    float acc02 = 0.0f;   // bimap/vote BCE terms (weight 0.2 at end)
    float acc1  = 0.0f;   // decouple terms

    // ==== load phase: lane = halo col 1..32 (in-tile cols, always in-image).
    // sigmoid/log-sigmoid once per element; conmap BCE fused while lp,x live:
    //   t*logp + (1-t)*log(1-p) = lp - (1-t)*x   (exact; clip dead for |x|<100)
    {
        const int wx = lane + 1;           // halo column
        const int gw = w0 + lane;          // global col, always valid
        #pragma unroll
        for (int j = 0; j < 3; j++) {
            int row = wrp + j * 8;
            if (row >= HH_) break;         // j==2 only for wrp<2
            int gh = h0 - 1 + row;
            bool inimg  = (unsigned)gh < H_;
            bool intile = (row >= 1) && (row <= TH);   // implies inimg
            long goff = ((long)(b * C_) * H_ + gh) * W_ + gw;
            unsigned mask = 0;
            #pragma unroll
            for (int c = 0; c < 8; c++) {
                float p = 0.0f, lp = -1e9f, x = 0.0f;
                if (inimg) {
                    x = cmap[goff + (long)c * (long)CHS];
                    sigmoid_pair(x, p, lp);
                }
                int si = (c * HH_ + row) * SROW + wx;
                s_p[si]  = p;
                s_lp[si] = lp;
                if (intile) {
                    float t = __ldcs(&con[goff + (long)c * (long)CHS]);
                    mask |= (t != 0.0f ? 1u : 0u) << c;
                    acc08 += fmaf(t - 1.0f, x, lp);   // lp - (1-t)*x
                }
            }
            if (intile) s_mask[(row - 1) * TW + lane] = (unsigned char)mask;
        }
    }
    // epilogue: halo cols 0 and 33 (8c * 18row * 2 = 288 elements)
    for (int idx = tid; idx < C_ * HH_ * 2; idx += NTHREADS) {
        int c   = idx / (HH_ * 2);
        int rem = idx - c * (HH_ * 2);
        int row = rem >> 1;
        int wx  = (rem & 1) ? 33 : 0;
        int gh  = h0 - 1 + row;
        int gw  = w0 - 1 + wx;
        float p = 0.0f, lp = -1e9f;
        if (((unsigned)gh < H_) && ((unsigned)gw < W_)) {
            float x = cmap[((long)(b * C_ + c) * H_ + gh) * W_ + gw];
            sigmoid_pair(x, p, lp);
        }
        int si = (c * HH_ + row) * SROW + wx;
        s_p[si]  = p;
        s_lp[si] = lp;
    }
    __syncthreads();

    // ==== compute phase: 1 px/lane, 2 rows/thread; conflict-free LDS only.
    // vote k: center ch k  x  ch 7-k at neighbor offset (DH[k], DW[k]).
    // MUFU cut: sum of log(1-v_k) over unselected k = log(prod of (1-v_k)).
    const int DH[8] = {-1, -1, -1,  0, 0,  1, 1, 1};
    const int DW[8] = {-1,  0,  1, -1, 1, -1, 0, 1};

    #pragma unroll
    for (int q = 0; q < 2; q++) {
        const int py = wrp + q * 8;          // tile row 0..15
        const int gh = h0 + py;
        const int gw = w0 + lane;
        const int sbase = (py + 1) * SROW + lane + 1;
        const unsigned mask = s_mask[py * TW + lane];

        float pc[8], lpc[8];
        #pragma unroll
        for (int c = 0; c < 8; c++) {
            int si = c * (HH_ * SROW) + sbase;
            pc[c]  = s_p[si];
            lpc[c] = s_lp[si];
        }

        float vmin = 1e30f, vsum = 0.0f, prod = 1.0f;
        #pragma unroll
        for (int k = 0; k < 8; k++) {
            int ni = (7 - k) * (HH_ * SROW) + (py + 1 + DH[k]) * SROW
                     + (lane + 1 + DW[k]);
            float np  = s_p[ni];
            float nlp = s_lp[ni];
            float v   = pc[k] * np;
            float omv = fmaf(-pc[k], np, 1.0f);              // 1 - v
            float lv  = fmaxf(lpc[k] + nlp, -100.0f);        // log(pa*pb), free
            bool  bit = (mask >> k) & 1u;
            acc02 += bit ? lv : 0.0f;
            prod  *= bit ? 1.0f : omv;                       // defer the log
            vmin = fminf(vmin, v);
            vsum += v;
        }
        acc02 += __logf(prod);   // = sum of log(1-v_k), k unselected; no clip
                                 // can bind: prod >= (1-smax^2)^8 >> e^-100

        // decouple / de loss (w=1.0): one logf via argument select
        bool  edge = (mask != 0u) && (mask != 0xFFu);
        float glo  = vsum * 0.125f;
        float da   = edge ? (1.0f - vmin) : glo;            // decouple_map
        float db   = edge ? vmin : (1.0f - glo);            // 1 - decouple_map
        float tt   = __ldcs(&target[((size_t)b * H_ + gh) * W_ + gw]);
        float arg  = (tt != 0.0f) ? da : db;
        acc1 += fmaxf(__logf(arg), -100.0f);
    }

    // ==== block reduction + global accumulate ==============================
    float acc = fmaf(0.8f, acc08, fmaf(0.2f, acc02, acc1));
    #pragma unroll
    for (int off = 16; off; off >>= 1)
        acc += __shfl_xor_sync(0xFFFFFFFFu, acc, off);

    __shared__ float warpsum[8];
    if (lane == 0) warpsum[wrp] = acc;
    __syncthreads();
    if (tid < 8) {
        float v = warpsum[tid];
        #pragma unroll
        for (int off = 4; off; off >>= 1)
            v += __shfl_xor_sync(0xFFu, v, off);
        if (tid == 0) atomicAdd(&g_acc, (double)v);
    }

    // ==== last block finalizes: write out, reset for next graph replay =====
    if (tid == 0) {
        __threadfence();
        unsigned t = atomicAdd(&g_tick, 1u);
        if (t == (unsigned)(NBLOCKS - 1)) {
            __threadfence();
            double total = atomicAdd(&g_acc, 0.0);
            out[0] = (float)(-total);
            g_acc  = 0.0;
            g_tick = 0u;
            __threadfence();
        }
    }
}

extern "C" void kernel_launch(void* const* d_in, const int* in_sizes, int n_in,
                              void* d_out, int out_size) {
    const float* cmap   = (const float*)d_in[0];
    const float* target = (const float*)d_in[1];
    const float* con    = (const float*)d_in[2];

    dim3 grid(W_ / TW, H_ / TH, B_);
    k_main<<<grid, NTHREADS>>>(cmap, target, con, (float*)d_out);
}